// round 15
// baseline (speedup 1.0000x reference)
#include <cuda_runtime.h>
#include <cuda_fp16.h>

#define N_NODES 100000
#define N_EDGES 1600000
#define DIM 128
#define CAP 64            // bucket capacity; overflow side-list handles the rest

// Scratch (allocation-free rule: __device__ globals)
__device__ __half g_xw[(size_t)N_NODES * DIM];        // 25.6 MB, fp16
__device__ float g_dis[N_NODES];
__device__ int   g_cnt[N_NODES];                      // per-node in-degree counters
__device__ int   g_slots[(size_t)N_NODES * CAP];      // 25.6 MB bucket storage
__device__ int   g_ovr[N_EDGES];                      // overflow rows (normally unused)
__device__ int   g_ovc[N_EDGES];                      // overflow cols
__device__ int   g_ovcnt;
__device__ int   g_orflag;  // OR of sampled odd int32 words; 0 => int64

// ---------------- zero counters + flag (runs on GEMM side stream) ----------------
__global__ void k_zero() {
    int i = blockIdx.x * blockDim.x + threadIdx.x;
    if (i < N_NODES) g_cnt[i] = 0;
    if (i == 0) { g_ovcnt = 0; g_orflag = 0; }
}

// ---------------- dtype detect: 2 blocks x 512 thr x 4 samples ----------------
__global__ void k_detect(const int* __restrict__ ei32) {
    int t = blockIdx.x * blockDim.x + threadIdx.x;    // 0..1023
    int acc = 0;
#pragma unroll
    for (int s = 0; s < 4; s++) {
        int j = t + s * 1024;                 // 0..4095
        long long idx = (long long)j * 390;   // spread over ~1.6M entries
        acc |= ei32[2 * idx + 1];
    }
    if (acc != 0) atomicOr(&g_orflag, 1);
}

// ---------------- single-pass place into fixed-capacity buckets (R11-proven) ----------------
__global__ void k_place(const int* __restrict__ ei32) {
    int t = blockIdx.x * blockDim.x + threadIdx.x;   // 0 .. N_EDGES/2-1
    if (t >= N_EDGES / 2) return;
    int r0, r1, c0, c1;
    if (g_orflag == 0) {     // int64: low words
        int4 vr = __ldg(&((const int4*)ei32)[t]);
        int4 vc = __ldg(&((const int4*)(ei32 + 2 * N_EDGES))[t]);
        r0 = vr.x; r1 = vr.z;
        c0 = vc.x; c1 = vc.z;
    } else {                 // int32
        int2 vr = __ldg(&((const int2*)ei32)[t]);
        int2 vc = __ldg(&((const int2*)(ei32 + N_EDGES))[t]);
        r0 = vr.x; r1 = vr.y;
        c0 = vc.x; c1 = vc.y;
    }
    int p0 = atomicAdd(&g_cnt[c0], 1);
    if (p0 < CAP) g_slots[(size_t)c0 * CAP + p0] = r0;
    else { int o = atomicAdd(&g_ovcnt, 1); g_ovr[o] = r0; g_ovc[o] = c0; }
    int p1 = atomicAdd(&g_cnt[c1], 1);
    if (p1 < CAP) g_slots[(size_t)c1 * CAP + p1] = r1;
    else { int o = atomicAdd(&g_ovcnt, 1); g_ovr[o] = r1; g_ovc[o] = c1; }
}

// ---------------- dis = rsqrt(deg+1) from final counts ----------------
__global__ void k_dis() {
    int i = blockIdx.x * blockDim.x + threadIdx.x;
    if (i < N_NODES) g_dis[i] = rsqrtf((float)(g_cnt[i] + 1));
}

// ---------------- tf32 tensor-core GEMM: g_xw = fp16(x @ W) (R4-proven) ----------------
__global__ __launch_bounds__(256) void k_gemm(const float* __restrict__ x,
                                              const float* __restrict__ W) {
    __shared__ unsigned As[128][36];
    __shared__ unsigned Bs[32][136];
    const int m0   = blockIdx.x * 128;
    const int tid  = threadIdx.x;
    const int warp = tid >> 5;
    const int lane = tid & 31;
    const int wm   = warp >> 1;
    const int wn   = warp & 1;
    const int qr   = lane >> 2;
    const int qc   = lane & 3;

    float acc[2][8][4];
#pragma unroll
    for (int mi = 0; mi < 2; mi++)
#pragma unroll
        for (int ni = 0; ni < 8; ni++)
#pragma unroll
            for (int j = 0; j < 4; j++) acc[mi][ni][j] = 0.f;

#pragma unroll 1
    for (int kt = 0; kt < 4; kt++) {
#pragma unroll
        for (int i = 0; i < 16; i++) {
            int idx = tid + i * 256;
            int r = idx >> 5, c = idx & 31;
            int gr = m0 + r;
            float v = (gr < N_NODES) ? __ldg(&x[(size_t)gr * DIM + kt * 32 + c]) : 0.f;
            unsigned u;
            asm("cvt.rna.tf32.f32 %0, %1;" : "=r"(u) : "f"(v));
            As[r][c] = u;
        }
#pragma unroll
        for (int i = 0; i < 16; i++) {
            int idx = tid + i * 256;
            int r = idx >> 7, c = idx & 127;
            float v = __ldg(&W[(kt * 32 + r) * DIM + c]);
            unsigned u;
            asm("cvt.rna.tf32.f32 %0, %1;" : "=r"(u) : "f"(v));
            Bs[r][c] = u;
        }
        __syncthreads();

#pragma unroll
        for (int ks = 0; ks < 4; ks++) {
            const int k0 = ks * 8;
            unsigned a[2][4], bf[8][2];
#pragma unroll
            for (int mi = 0; mi < 2; mi++) {
                int rb = wm * 32 + mi * 16;
                a[mi][0] = As[rb + qr][k0 + qc];
                a[mi][1] = As[rb + qr + 8][k0 + qc];
                a[mi][2] = As[rb + qr][k0 + qc + 4];
                a[mi][3] = As[rb + qr + 8][k0 + qc + 4];
            }
#pragma unroll
            for (int ni = 0; ni < 8; ni++) {
                int cb = wn * 64 + ni * 8;
                bf[ni][0] = Bs[k0 + qc][cb + qr];
                bf[ni][1] = Bs[k0 + qc + 4][cb + qr];
            }
#pragma unroll
            for (int mi = 0; mi < 2; mi++)
#pragma unroll
                for (int ni = 0; ni < 8; ni++) {
                    asm volatile(
                        "mma.sync.aligned.m16n8k8.row.col.f32.tf32.tf32.f32 "
                        "{%0,%1,%2,%3}, {%4,%5,%6,%7}, {%8,%9}, {%0,%1,%2,%3};"
                        : "+f"(acc[mi][ni][0]), "+f"(acc[mi][ni][1]),
                          "+f"(acc[mi][ni][2]), "+f"(acc[mi][ni][3])
                        : "r"(a[mi][0]), "r"(a[mi][1]), "r"(a[mi][2]), "r"(a[mi][3]),
                          "r"(bf[ni][0]), "r"(bf[ni][1]));
                }
        }
        __syncthreads();
    }

#pragma unroll
    for (int mi = 0; mi < 2; mi++) {
        int r0 = m0 + wm * 32 + mi * 16 + qr;
        int r1 = r0 + 8;
#pragma unroll
        for (int ni = 0; ni < 8; ni++) {
            int cb = wn * 64 + ni * 8 + qc * 2;
            if (r0 < N_NODES)
                *(__half2*)&g_xw[(size_t)r0 * DIM + cb] =
                    __floats2half2_rn(acc[mi][ni][0], acc[mi][ni][1]);
            if (r1 < N_NODES)
                *(__half2*)&g_xw[(size_t)r1 * DIM + cb] =
                    __floats2half2_rn(acc[mi][ni][2], acc[mi][ni][3]);
        }
    }
}

// ---------------- bucket gather: batch-loaded indices, depth-1 row loads ----------------
__device__ __forceinline__ void hacc(float* a, const uint4& u, float w) {
    float2 f0 = __half22float2(*(const __half2*)&u.x);
    float2 f1 = __half22float2(*(const __half2*)&u.y);
    float2 f2 = __half22float2(*(const __half2*)&u.z);
    float2 f3 = __half22float2(*(const __half2*)&u.w);
    a[0] += f0.x * w; a[1] += f0.y * w;
    a[2] += f1.x * w; a[3] += f1.y * w;
    a[4] += f2.x * w; a[5] += f2.y * w;
    a[6] += f3.x * w; a[7] += f3.y * w;
}

__global__ __launch_bounds__(256) void k_gather(const float* __restrict__ b,
                                                float* __restrict__ out) {
    int n    = (blockIdx.x * blockDim.x + threadIdx.x) >> 5;
    int lane = threadIdx.x & 31;
    if (n >= N_NODES) return;
    int half = lane >> 4;      // 0 or 1
    int l16  = lane & 15;
    const unsigned FULL = 0xffffffffu;

    const uint4* xw4 = (const uint4*)g_xw;   // row stride = 16 uint4
    const int* bucket = g_slots + (size_t)n * CAP;
    float dn = g_dis[n];

    int deg = g_cnt[n];
    int end = (deg < CAP) ? deg : CAP;

    // Batch-load all <=64 edge indices (2 warp-LDGs) and weights (2 warp-LDGs).
    // One 2-deep chain per node instead of per iteration.
    int i0 = (lane < end)      ? __ldg(&bucket[lane])      : n;
    int i1 = (lane + 32 < end) ? __ldg(&bucket[lane + 32]) : n;
    float w0 = (lane < end)      ? __ldg(&g_dis[i0]) * dn : 0.f;
    float w1 = (lane + 32 < end) ? __ldg(&g_dis[i1]) * dn : 0.f;

    float a[8];
#pragma unroll
    for (int i = 0; i < 8; i++) a[i] = 0.f;

    // self-loop: half 0 carries weight dn*dn, half 1 contributes 0
    {
        uint4 u = __ldg(&xw4[(size_t)n * 16 + l16]);
        hacc(a, u, (half == 0) ? dn * dn : 0.f);
    }

    int e = 0;
    // 8 edges per warp-iteration; 4 independent row loads per lane in flight
    for (; e + 7 < end; e += 8) {
        int r[4]; float w[4];
#pragma unroll
        for (int k = 0; k < 4; k++) {
            int s = e + 2 * k + half;
            int   rA = __shfl_sync(FULL, i0, s & 31);
            int   rB = __shfl_sync(FULL, i1, s & 31);
            float wA = __shfl_sync(FULL, w0, s & 31);
            float wB = __shfl_sync(FULL, w1, s & 31);
            r[k] = (s < 32) ? rA : rB;
            w[k] = (s < 32) ? wA : wB;
        }
        uint4 u0 = __ldg(&xw4[(size_t)r[0] * 16 + l16]);
        uint4 u1 = __ldg(&xw4[(size_t)r[1] * 16 + l16]);
        uint4 u2 = __ldg(&xw4[(size_t)r[2] * 16 + l16]);
        uint4 u3 = __ldg(&xw4[(size_t)r[3] * 16 + l16]);
        hacc(a, u0, w[0]);
        hacc(a, u1, w[1]);
        hacc(a, u2, w[2]);
        hacc(a, u3, w[3]);
    }
    // tail: predicated 2 edges per iteration
    for (; e < end; e += 2) {
        int s = e + half;
        int   rA = __shfl_sync(FULL, i0, s & 31);
        int   rB = __shfl_sync(FULL, i1, s & 31);
        float wA = __shfl_sync(FULL, w0, s & 31);
        float wB = __shfl_sync(FULL, w1, s & 31);
        bool valid = s < end;
        int   rr = valid ? ((s < 32) ? rA : rB) : n;
        float ww = valid ? ((s < 32) ? wA : wB) : 0.f;
        uint4 u = __ldg(&xw4[(size_t)rr * 16 + l16]);
        hacc(a, u, ww);
    }

    // overflow edges (normally zero) — exact correctness for any input
    int ov = g_ovcnt;
    for (int i = 0; i < ov; i++) {
        if (__ldg(&g_ovc[i]) == n) {
            int r = __ldg(&g_ovr[i]);
            float w = __ldg(&g_dis[r]) * dn;
            uint4 u = __ldg(&xw4[(size_t)r * 16 + l16]);
            hacc(a, u, (half == 0) ? w : 0.f);
        }
    }

    // combine halves
#pragma unroll
    for (int i = 0; i < 8; i++)
        a[i] += __shfl_xor_sync(FULL, a[i], 16);

    if (half == 0) {
        float4 b0 = ((const float4*)b)[l16 * 2];
        float4 b1 = ((const float4*)b)[l16 * 2 + 1];
        float4 o0 = make_float4(fmaxf(a[0] + b0.x, 0.f), fmaxf(a[1] + b0.y, 0.f),
                                fmaxf(a[2] + b0.z, 0.f), fmaxf(a[3] + b0.w, 0.f));
        float4 o1 = make_float4(fmaxf(a[4] + b1.x, 0.f), fmaxf(a[5] + b1.y, 0.f),
                                fmaxf(a[6] + b1.z, 0.f), fmaxf(a[7] + b1.w, 0.f));
        ((float4*)out)[(size_t)n * 32 + l16 * 2]     = o0;
        ((float4*)out)[(size_t)n * 32 + l16 * 2 + 1] = o1;
    }
}

extern "C" void kernel_launch(void* const* d_in, const int* in_sizes, int n_in,
                              void* d_out, int out_size) {
    // Identify inputs by element count:
    //   x: 12,800,000   edge_index: 3,200,000   W: 16,384   b: 128
    const float* x  = nullptr;
    const void*  ei = nullptr;
    const float* W  = nullptr;
    const float* b  = nullptr;
    for (int i = 0; i < n_in; i++) {
        switch (in_sizes[i]) {
            case 12800000: x  = (const float*)d_in[i]; break;
            case 3200000:  ei = d_in[i];               break;
            case 16384:    W  = (const float*)d_in[i]; break;
            case 128:      b  = (const float*)d_in[i]; break;
            default: break;
        }
    }
    float* out = (float*)d_out;
    const int* ei32 = (const int*)ei;

    // Side stream: zero counters+flag, then GEMM.
    cudaStream_t s2;
    cudaStreamCreateWithFlags(&s2, cudaStreamNonBlocking);
    cudaEvent_t ev_fork, ev_zero, ev_join;
    cudaEventCreateWithFlags(&ev_fork, cudaEventDisableTiming);
    cudaEventCreateWithFlags(&ev_zero, cudaEventDisableTiming);
    cudaEventCreateWithFlags(&ev_join, cudaEventDisableTiming);

    cudaEventRecord(ev_fork, 0);
    cudaStreamWaitEvent(s2, ev_fork, 0);
    k_zero<<<(N_NODES + 255) / 256, 256, 0, s2>>>();
    cudaEventRecord(ev_zero, s2);
    k_gemm<<<(N_NODES + 127) / 128, 256, 0, s2>>>(x, W);
    cudaEventRecord(ev_join, s2);

    // main-stream chain: (wait zero) -> detect -> place -> dis -> (wait gemm) -> gather
    cudaStreamWaitEvent(0, ev_zero, 0);
    k_detect<<<2, 512>>>(ei32);
    k_place<<<(N_EDGES / 2 + 255) / 256, 256>>>(ei32);
    k_dis<<<(N_NODES + 255) / 256, 256>>>();

    cudaStreamWaitEvent(0, ev_join, 0);
    {
        long long total_threads = (long long)N_NODES * 32;
        int blocks = (int)((total_threads + 255) / 256);
        k_gather<<<blocks, 256>>>(b, out);
    }
}

// round 16
// speedup vs baseline: 1.0911x; 1.0911x over previous
#include <cuda_runtime.h>
#include <cuda_fp16.h>

#define N_NODES 100000
#define N_EDGES 1600000
#define DIM 128
#define CAP 64            // bucket capacity; overflow side-list handles the rest

// Scratch (allocation-free rule: __device__ globals)
__device__ __half g_xw[(size_t)N_NODES * DIM];        // 25.6 MB, fp16
__device__ float g_dis[N_NODES];
__device__ int   g_cnt[N_NODES];                      // per-node in-degree counters
__device__ int   g_slots[(size_t)N_NODES * CAP];      // 25.6 MB bucket storage
__device__ int   g_ovr[N_EDGES];                      // overflow rows (normally unused)
__device__ int   g_ovc[N_EDGES];                      // overflow cols
__device__ int   g_ovcnt;
__device__ int   g_orflag;  // OR of sampled odd int32 words; 0 => int64

// ---------------- zero counters + flag (runs on GEMM side stream) ----------------
__global__ void k_zero() {
    int i = blockIdx.x * blockDim.x + threadIdx.x;
    if (i < N_NODES) g_cnt[i] = 0;
    if (i == 0) { g_ovcnt = 0; g_orflag = 0; }
}

// ---------------- dtype detect: 2 blocks x 512 thr x 4 samples ----------------
__global__ void k_detect(const int* __restrict__ ei32) {
    int t = blockIdx.x * blockDim.x + threadIdx.x;    // 0..1023
    int acc = 0;
#pragma unroll
    for (int s = 0; s < 4; s++) {
        int j = t + s * 1024;                 // 0..4095
        long long idx = (long long)j * 390;   // spread over ~1.6M entries
        acc |= ei32[2 * idx + 1];
    }
    if (acc != 0) atomicOr(&g_orflag, 1);
}

// ---------------- single-pass place into fixed-capacity buckets (R11-proven) ----------------
__global__ void k_place(const int* __restrict__ ei32) {
    int t = blockIdx.x * blockDim.x + threadIdx.x;   // 0 .. N_EDGES/2-1
    if (t >= N_EDGES / 2) return;
    int r0, r1, c0, c1;
    if (g_orflag == 0) {     // int64: low words
        int4 vr = __ldg(&((const int4*)ei32)[t]);
        int4 vc = __ldg(&((const int4*)(ei32 + 2 * N_EDGES))[t]);
        r0 = vr.x; r1 = vr.z;
        c0 = vc.x; c1 = vc.z;
    } else {                 // int32
        int2 vr = __ldg(&((const int2*)ei32)[t]);
        int2 vc = __ldg(&((const int2*)(ei32 + N_EDGES))[t]);
        r0 = vr.x; r1 = vr.y;
        c0 = vc.x; c1 = vc.y;
    }
    int p0 = atomicAdd(&g_cnt[c0], 1);
    if (p0 < CAP) g_slots[(size_t)c0 * CAP + p0] = r0;
    else { int o = atomicAdd(&g_ovcnt, 1); g_ovr[o] = r0; g_ovc[o] = c0; }
    int p1 = atomicAdd(&g_cnt[c1], 1);
    if (p1 < CAP) g_slots[(size_t)c1 * CAP + p1] = r1;
    else { int o = atomicAdd(&g_ovcnt, 1); g_ovr[o] = r1; g_ovc[o] = c1; }
}

// ---------------- dis = rsqrt(deg+1) from final counts ----------------
__global__ void k_dis() {
    int i = blockIdx.x * blockDim.x + threadIdx.x;
    if (i < N_NODES) g_dis[i] = rsqrtf((float)(g_cnt[i] + 1));
}

// ---------------- tf32 tensor-core GEMM: g_xw = fp16(x @ W) (R4-proven) ----------------
__global__ __launch_bounds__(256) void k_gemm(const float* __restrict__ x,
                                              const float* __restrict__ W) {
    __shared__ unsigned As[128][36];
    __shared__ unsigned Bs[32][136];
    const int m0   = blockIdx.x * 128;
    const int tid  = threadIdx.x;
    const int warp = tid >> 5;
    const int lane = tid & 31;
    const int wm   = warp >> 1;
    const int wn   = warp & 1;
    const int qr   = lane >> 2;
    const int qc   = lane & 3;

    float acc[2][8][4];
#pragma unroll
    for (int mi = 0; mi < 2; mi++)
#pragma unroll
        for (int ni = 0; ni < 8; ni++)
#pragma unroll
            for (int j = 0; j < 4; j++) acc[mi][ni][j] = 0.f;

#pragma unroll 1
    for (int kt = 0; kt < 4; kt++) {
#pragma unroll
        for (int i = 0; i < 16; i++) {
            int idx = tid + i * 256;
            int r = idx >> 5, c = idx & 31;
            int gr = m0 + r;
            float v = (gr < N_NODES) ? __ldg(&x[(size_t)gr * DIM + kt * 32 + c]) : 0.f;
            unsigned u;
            asm("cvt.rna.tf32.f32 %0, %1;" : "=r"(u) : "f"(v));
            As[r][c] = u;
        }
#pragma unroll
        for (int i = 0; i < 16; i++) {
            int idx = tid + i * 256;
            int r = idx >> 7, c = idx & 127;
            float v = __ldg(&W[(kt * 32 + r) * DIM + c]);
            unsigned u;
            asm("cvt.rna.tf32.f32 %0, %1;" : "=r"(u) : "f"(v));
            Bs[r][c] = u;
        }
        __syncthreads();

#pragma unroll
        for (int ks = 0; ks < 4; ks++) {
            const int k0 = ks * 8;
            unsigned a[2][4], bf[8][2];
#pragma unroll
            for (int mi = 0; mi < 2; mi++) {
                int rb = wm * 32 + mi * 16;
                a[mi][0] = As[rb + qr][k0 + qc];
                a[mi][1] = As[rb + qr + 8][k0 + qc];
                a[mi][2] = As[rb + qr][k0 + qc + 4];
                a[mi][3] = As[rb + qr + 8][k0 + qc + 4];
            }
#pragma unroll
            for (int ni = 0; ni < 8; ni++) {
                int cb = wn * 64 + ni * 8;
                bf[ni][0] = Bs[k0 + qc][cb + qr];
                bf[ni][1] = Bs[k0 + qc + 4][cb + qr];
            }
#pragma unroll
            for (int mi = 0; mi < 2; mi++)
#pragma unroll
                for (int ni = 0; ni < 8; ni++) {
                    asm volatile(
                        "mma.sync.aligned.m16n8k8.row.col.f32.tf32.tf32.f32 "
                        "{%0,%1,%2,%3}, {%4,%5,%6,%7}, {%8,%9}, {%0,%1,%2,%3};"
                        : "+f"(acc[mi][ni][0]), "+f"(acc[mi][ni][1]),
                          "+f"(acc[mi][ni][2]), "+f"(acc[mi][ni][3])
                        : "r"(a[mi][0]), "r"(a[mi][1]), "r"(a[mi][2]), "r"(a[mi][3]),
                          "r"(bf[ni][0]), "r"(bf[ni][1]));
                }
        }
        __syncthreads();
    }

#pragma unroll
    for (int mi = 0; mi < 2; mi++) {
        int r0 = m0 + wm * 32 + mi * 16 + qr;
        int r1 = r0 + 8;
#pragma unroll
        for (int ni = 0; ni < 8; ni++) {
            int cb = wn * 64 + ni * 8 + qc * 2;
            if (r0 < N_NODES)
                *(__half2*)&g_xw[(size_t)r0 * DIM + cb] =
                    __floats2half2_rn(acc[mi][ni][0], acc[mi][ni][1]);
            if (r1 < N_NODES)
                *(__half2*)&g_xw[(size_t)r1 * DIM + cb] =
                    __floats2half2_rn(acc[mi][ni][2], acc[mi][ni][3]);
        }
    }
}

// ---------------- bucket gather: R14 structure + software-pipelined idx/dis prefetch ----------------
__device__ __forceinline__ void hacc(float* a, const uint4& u, float w) {
    float2 f0 = __half22float2(*(const __half2*)&u.x);
    float2 f1 = __half22float2(*(const __half2*)&u.y);
    float2 f2 = __half22float2(*(const __half2*)&u.z);
    float2 f3 = __half22float2(*(const __half2*)&u.w);
    a[0] += f0.x * w; a[1] += f0.y * w;
    a[2] += f1.x * w; a[3] += f1.y * w;
    a[4] += f2.x * w; a[5] += f2.y * w;
    a[6] += f3.x * w; a[7] += f3.y * w;
}

__global__ __launch_bounds__(256) void k_gather(const float* __restrict__ b,
                                                float* __restrict__ out) {
    int n    = (blockIdx.x * blockDim.x + threadIdx.x) >> 5;
    int lane = threadIdx.x & 31;
    if (n >= N_NODES) return;
    int half = lane >> 4;      // 0 or 1
    int l16  = lane & 15;
    const unsigned FULL = 0xffffffffu;

    const uint4* xw4 = (const uint4*)g_xw;   // row stride = 16 uint4
    const int* bucket = g_slots + (size_t)n * CAP;
    float dn = g_dis[n];

    float a[8];
#pragma unroll
    for (int i = 0; i < 8; i++) a[i] = 0.f;

    // self-loop: half 0 carries weight dn*dn, half 1 contributes 0
    {
        uint4 u = __ldg(&xw4[(size_t)n * 16 + l16]);
        hacc(a, u, (half == 0) ? dn * dn : 0.f);
    }

    int deg = g_cnt[n];
    int end = (deg < CAP) ? deg : CAP;

    int e = 0;
    // pipelined main loop: 4 edges per warp-iteration (2 per half-warp).
    // Current group's (idx, w) are preloaded; the next group's idx/dis loads
    // issue while this group's row loads are in flight.
    int cr0 = 0, cr1 = 0; float cw0 = 0.f, cw1 = 0.f;
    if (e + 3 < end) {
        cr0 = __ldg(&bucket[e + half]);
        cr1 = __ldg(&bucket[e + 2 + half]);
        cw0 = __ldg(&g_dis[cr0]) * dn;
        cw1 = __ldg(&g_dis[cr1]) * dn;
    }
    for (; e + 3 < end; e += 4) {
        // issue current rows (long latency)
        uint4 u0 = __ldg(&xw4[(size_t)cr0 * 16 + l16]);
        uint4 u1 = __ldg(&xw4[(size_t)cr1 * 16 + l16]);
        // prefetch next group's idx + dis under the row wait
        int nr0 = 0, nr1 = 0; float nw0 = 0.f, nw1 = 0.f;
        bool more = (e + 7 < end);
        if (more) {
            nr0 = __ldg(&bucket[e + 4 + half]);
            nr1 = __ldg(&bucket[e + 6 + half]);
            nw0 = __ldg(&g_dis[nr0]) * dn;
            nw1 = __ldg(&g_dis[nr1]) * dn;
        }
        // consume rows
        hacc(a, u0, cw0);
        hacc(a, u1, cw1);
        cr0 = nr0; cr1 = nr1; cw0 = nw0; cw1 = nw1;
    }
    // tail: predicated 2 edges per iteration
    for (; e < end; e += 2) {
        int idx = e + half;
        bool valid = idx < end;
        int r0 = valid ? __ldg(&bucket[idx]) : n;
        float w0 = valid ? __ldg(&g_dis[r0]) * dn : 0.f;
        uint4 u0 = __ldg(&xw4[(size_t)r0 * 16 + l16]);
        hacc(a, u0, w0);
    }

    // overflow edges (normally zero) — exact correctness for any input
    int ov = g_ovcnt;
    for (int i = 0; i < ov; i++) {
        if (__ldg(&g_ovc[i]) == n) {
            int r = __ldg(&g_ovr[i]);
            float w = __ldg(&g_dis[r]) * dn;
            uint4 u = __ldg(&xw4[(size_t)r * 16 + l16]);
            hacc(a, u, (half == 0) ? w : 0.f);
        }
    }

    // combine halves
#pragma unroll
    for (int i = 0; i < 8; i++)
        a[i] += __shfl_xor_sync(FULL, a[i], 16);

    if (half == 0) {
        float4 b0 = ((const float4*)b)[l16 * 2];
        float4 b1 = ((const float4*)b)[l16 * 2 + 1];
        float4 o0 = make_float4(fmaxf(a[0] + b0.x, 0.f), fmaxf(a[1] + b0.y, 0.f),
                                fmaxf(a[2] + b0.z, 0.f), fmaxf(a[3] + b0.w, 0.f));
        float4 o1 = make_float4(fmaxf(a[4] + b1.x, 0.f), fmaxf(a[5] + b1.y, 0.f),
                                fmaxf(a[6] + b1.z, 0.f), fmaxf(a[7] + b1.w, 0.f));
        ((float4*)out)[(size_t)n * 32 + l16 * 2]     = o0;
        ((float4*)out)[(size_t)n * 32 + l16 * 2 + 1] = o1;
    }
}

extern "C" void kernel_launch(void* const* d_in, const int* in_sizes, int n_in,
                              void* d_out, int out_size) {
    // Identify inputs by element count:
    //   x: 12,800,000   edge_index: 3,200,000   W: 16,384   b: 128
    const float* x  = nullptr;
    const void*  ei = nullptr;
    const float* W  = nullptr;
    const float* b  = nullptr;
    for (int i = 0; i < n_in; i++) {
        switch (in_sizes[i]) {
            case 12800000: x  = (const float*)d_in[i]; break;
            case 3200000:  ei = d_in[i];               break;
            case 16384:    W  = (const float*)d_in[i]; break;
            case 128:      b  = (const float*)d_in[i]; break;
            default: break;
        }
    }
    float* out = (float*)d_out;
    const int* ei32 = (const int*)ei;

    // Side stream: zero counters+flag, then GEMM.
    cudaStream_t s2;
    cudaStreamCreateWithFlags(&s2, cudaStreamNonBlocking);
    cudaEvent_t ev_fork, ev_zero, ev_join;
    cudaEventCreateWithFlags(&ev_fork, cudaEventDisableTiming);
    cudaEventCreateWithFlags(&ev_zero, cudaEventDisableTiming);
    cudaEventCreateWithFlags(&ev_join, cudaEventDisableTiming);

    cudaEventRecord(ev_fork, 0);
    cudaStreamWaitEvent(s2, ev_fork, 0);
    k_zero<<<(N_NODES + 255) / 256, 256, 0, s2>>>();
    cudaEventRecord(ev_zero, s2);
    k_gemm<<<(N_NODES + 127) / 128, 256, 0, s2>>>(x, W);
    cudaEventRecord(ev_join, s2);

    // main-stream chain: (wait zero) -> detect -> place -> dis -> (wait gemm) -> gather
    cudaStreamWaitEvent(0, ev_zero, 0);
    k_detect<<<2, 512>>>(ei32);
    k_place<<<(N_EDGES / 2 + 255) / 256, 256>>>(ei32);
    k_dis<<<(N_NODES + 255) / 256, 256>>>();

    cudaStreamWaitEvent(0, ev_join, 0);
    {
        long long total_threads = (long long)N_NODES * 32;
        int blocks = (int)((total_threads + 255) / 256);
        k_gather<<<blocks, 256>>>(b, out);
    }
}